// round 13
// baseline (speedup 1.0000x reference)
#include <cuda_runtime.h>
#include <stdint.h>

#define BATCH   32768
#define NTREE   256
#define NNODE   2047
#define NFEAT   256
#define NCLS    8
#define DEPTH   10
#define SCHUNK  128
#define THREADS 512           // 128 samples x 4 tree-lanes (2 chains each)
#define GTREES  8
#define NCHUNK  (BATCH / SCHUNK)          // 256
#define NGROUPS (NTREE / GTREES)          // 32
#define NITEMS  (NCHUNK * NGROUPS)        // 8192, chunk-major
#define NSLOT   1024          // 8KB slab per tree (1023 internal nodes used)
#define GRPBYTES (GTREES * NSLOT * 8)     // 65536

// smem map: [0,128K) x-tile | [128K,192K) node buffer | [192K,+9K) idx x2 | mbar
#define SM_X      0
#define SM_NODES  131072
#define SM_IDX    196608
#define IDX_PITCH 9
#define IDX_BYTES (SCHUNK * IDX_PITCH * 4)   // 4608
#define SM_MBAR   (196608 + 2 * IDX_BYTES)
#define SM_TOTAL  (SM_MBAR + 16)

__device__ uint2 g_nodes2[NTREE * NSLOT];   // internal nodes: {thr bits, feat*512}
__device__ float g_xT[NFEAT * BATCH];       // x transposed [feature][sample]
__device__ unsigned g_arrive = 0;           // grid-barrier arrival counter
__device__ volatile unsigned g_release = 0; // grid-barrier epoch (monotonic across replays)

// ---------------- helpers ----------------
__device__ __forceinline__ void stage_x(char* sm, int s0, int tid) {
    float4* xs4 = (float4*)(sm + SM_X);
    #pragma unroll
    for (int j = 0; j < 16; j++) {
        int i4 = tid + THREADS * j;                 // 8192 float4
        int f = i4 >> 5, o = i4 & 31;
        xs4[i4] = *(const float4*)(g_xT + (size_t)f * BATCH + s0 + o * 4);
    }
}

__device__ __forceinline__ void bulk_fetch_nodes(unsigned dst, int g, unsigned mbar) {
    // one-shot 64KB DMA: expect_tx + bulk copy (caller: single thread)
    asm volatile("mbarrier.arrive.expect_tx.shared.b64 _, [%0], %1;"
                 :: "r"(mbar), "r"((unsigned)GRPBYTES) : "memory");
    const char* src = (const char*)g_nodes2 + (size_t)g * GRPBYTES;
    asm volatile("cp.async.bulk.shared::cta.global.mbarrier::complete_tx::bytes "
                 "[%0], [%1], %2, [%3];"
                 :: "r"(dst), "l"(src), "r"((unsigned)GRPBYTES), "r"(mbar) : "memory");
}

__device__ __forceinline__ void mbar_wait(unsigned mbar, unsigned parity) {
    unsigned done;
    asm volatile("{\n\t.reg .pred p;\n\t"
                 "mbarrier.try_wait.parity.acquire.cta.shared::cta.b64 p, [%1], %2;\n\t"
                 "selp.b32 %0, 1, 0, p;\n\t}"
                 : "=r"(done) : "r"(mbar), "r"(parity) : "memory");
    if (!done) {
        asm volatile("{\n\t.reg .pred P1;\n\t"
                     "W%=:\n\t"
                     "mbarrier.try_wait.parity.acquire.cta.shared::cta.b64 P1, [%0], %1, 0x989680;\n\t"
                     "@P1 bra.uni D%=;\n\t"
                     "bra.uni W%=;\n\t"
                     "D%=:\n\t}"
                     :: "r"(mbar), "r"(parity) : "memory");
    }
}

// ---------------- fused persistent kernel: prep + grid barrier + traversal ----------------
__global__ __launch_bounds__(THREADS, 1)
void traverse_k(const float* __restrict__ x,
                const int* __restrict__ features,
                const float* __restrict__ thresholds,
                const float* __restrict__ values,
                float* __restrict__ out, int nsm) {
    extern __shared__ char sm[];
    int tid = threadIdx.x;

    // ======== PHASE 0: fused prep (block-strided slices) ========
    {
        // transpose x -> g_xT, 4 tiles of 32x32 per iteration, exactly-once coverage
        float (*tile)[32][33] = (float(*)[32][33])sm;
        int sub = tid >> 7;               // 0..3: tile within quad
        int w   = (tid >> 5) & 3;         // warp within 128-thread sub-block
        int lx  = tid & 31;
        for (int tb = blockIdx.x * 4; tb < (NFEAT / 32) * (BATCH / 32); tb += nsm * 4) {
            int T = tb + sub;
            int f0 = (T & 7) * 32, s0g = (T >> 3) * 32;
            #pragma unroll
            for (int j = 0; j < 8; j++) {
                int r = w * 8 + j;
                tile[sub][r][lx] = x[(size_t)(s0g + r) * NFEAT + f0 + lx];  // coalesced
            }
            __syncthreads();
            #pragma unroll
            for (int j = 0; j < 8; j++) {
                int r = w * 8 + j;
                g_xT[(size_t)(f0 + r) * BATCH + s0g + lx] = tile[sub][lx][r]; // coalesced
            }
            __syncthreads();
        }
        // pack internal nodes -> g_nodes2
        for (int i = blockIdx.x * THREADS + tid; i < NTREE * 1023; i += nsm * THREADS) {
            int t = i / 1023;
            int n = i - t * 1023;
            int src = t * NNODE + n;
            uint2 v;
            v.x = __float_as_uint(thresholds[src]);
            v.y = (unsigned)features[src] * (SCHUNK * 4);
            g_nodes2[t * NSLOT + n] = v;
        }
        // device-wide sense-reversal barrier (all nsm blocks co-resident: grid == #SMs)
        __syncthreads();
        if (tid == 0) {
            __threadfence();                      // publish this block's prep writes
            unsigned r0 = g_release;              // epoch before this call's release
            unsigned a = atomicAdd(&g_arrive, 1);
            if (a == (unsigned)nsm - 1) {
                g_arrive = 0;                     // reset for next replay
                __threadfence();
                g_release = r0 + 1;               // release everyone
            } else {
                while (g_release == r0) __nanosleep(128);
            }
            __threadfence();                      // acquire all blocks' prep writes
        }
        __syncthreads();
    }

    // ======== PHASE 1: traversal (proven R10 core, unchanged) ========
    unsigned smbase;
    asm("{ .reg .u64 t; cvta.to.shared.u64 t, %1; cvt.u32.u64 %0, t; }"
        : "=r"(smbase) : "l"(sm));
    unsigned mbar = smbase + SM_MBAR;

    int istart = (int)((long long)blockIdx.x * NITEMS / nsm);
    int iend   = (int)((long long)(blockIdx.x + 1) * NITEMS / nsm);

    int sl = tid & (SCHUNK - 1);
    int tl = tid >> 7;                         // 0..3
    unsigned xaddr = smbase + SM_X + sl * 4;
    int tA = 2 * tl, tB = 2 * tl + 1;
    unsigned baseA = smbase + SM_NODES + tA * (NSLOT * 8);
    unsigned baseB = smbase + SM_NODES + tB * (NSLOT * 8);
    unsigned cA = 8u - baseA, cB = 8u - baseB;

    if (tid == 0)
        asm volatile("mbarrier.init.shared.b64 [%0], 1;" :: "r"(mbar) : "memory");
    __syncthreads();
    if (tid == 0) bulk_fetch_nodes(smbase + SM_NODES, istart & (NGROUPS - 1), mbar);
    int cur_chunk = istart >> 5;
    stage_x(sm, cur_chunk * SCHUNK, tid);
    __syncthreads();                            // x visible

    float4 vreg[4];
    float* prev_obase = out;

    for (int i = istart; i < iend; i++) {
        int k = i - istart;
        int chunk = i >> 5;
        int g = i & (NGROUPS - 1);
        int s0 = chunk * SCHUNK;
        int t0 = g * GTREES;

        if (chunk != cur_chunk) {               // all threads past prev barrier
            stage_x(sm, s0, tid);
            cur_chunk = chunk;
            __syncthreads();                    // x visible before traversal
        }

        // issue prev item's values gather (long-latency LDGs before the wait)
        if (i > istart) {
            const unsigned* rb = (const unsigned*)(sm + SM_IDX + ((i - 1) & 1) * IDX_BYTES);
            #pragma unroll
            for (int j = 0; j < 4; j++) {
                int e = tid + THREADS * j;
                int sl2 = e >> 4, tg = (e >> 1) & 7, half = e & 1;
                unsigned vrow = rb[sl2 * IDX_PITCH + tg];
                vreg[j] = __ldg((const float4*)values + (size_t)vrow * 2 + half);
            }
        }

        mbar_wait(mbar, (unsigned)(k & 1));     // nodes[i] staged (acquire)

        // ---- traversal: 2 interleaved chains, all loads from shared
        unsigned oA = baseA, oB = baseB;
        #pragma unroll
        for (int d = 0; d < DEPTH; d++) {
            unsigned ax, ay, bx, by;
            asm("ld.shared.v2.u32 {%0,%1}, [%2];" : "=r"(ax), "=r"(ay) : "r"(oA));
            asm("ld.shared.v2.u32 {%0,%1}, [%2];" : "=r"(bx), "=r"(by) : "r"(oB));
            float fa, fb;
            asm("ld.shared.f32 %0, [%1];" : "=f"(fa) : "r"(xaddr + ay));
            asm("ld.shared.f32 %0, [%1];" : "=f"(fb) : "r"(xaddr + by));
            oA = oA * 2u + cA + ((fa >= __uint_as_float(ax)) ? 8u : 0u);
            oB = oB * 2u + cB + ((fb >= __uint_as_float(bx)) ? 8u : 0u);
        }
        unsigned leafA = (oA - baseA) >> 3;     // 1023..2046
        unsigned leafB = (oB - baseB) >> 3;

        // ---- store prev item's gathered values (coalesced)
        if (i > istart) {
            #pragma unroll
            for (int j = 0; j < 4; j++) {
                int e = tid + THREADS * j;
                int sl2 = e >> 4, tg = (e >> 1) & 7, half = e & 1;
                *(float4*)(prev_obase + (size_t)sl2 * (NTREE * NCLS) + tg * NCLS + half * 4) = vreg[j];
            }
        }

        // ---- publish this item's values-row indices (pitch 9, conflict-free)
        {
            unsigned* wb = (unsigned*)(sm + SM_IDX + (i & 1) * IDX_BYTES);
            wb[sl * IDX_PITCH + tA] = (unsigned)(t0 + tA) * NNODE + leafA;
            wb[sl * IDX_PITCH + tB] = (unsigned)(t0 + tB) * NNODE + leafB;
        }
        __syncthreads();                        // idx visible; node reads done

        if (i + 1 < iend && tid == 0)
            bulk_fetch_nodes(smbase + SM_NODES, (i + 1) & (NGROUPS - 1), mbar);

        prev_obase = out + (size_t)s0 * (NTREE * NCLS) + t0 * NCLS;
    }

    // epilogue: gather + store for the last item
    {
        const unsigned* rb = (const unsigned*)(sm + SM_IDX + ((iend - 1) & 1) * IDX_BYTES);
        #pragma unroll
        for (int j = 0; j < 4; j++) {
            int e = tid + THREADS * j;
            int sl2 = e >> 4, tg = (e >> 1) & 7, half = e & 1;
            unsigned vrow = rb[sl2 * IDX_PITCH + tg];
            vreg[j] = __ldg((const float4*)values + (size_t)vrow * 2 + half);
        }
        #pragma unroll
        for (int j = 0; j < 4; j++) {
            int e = tid + THREADS * j;
            int sl2 = e >> 4, tg = (e >> 1) & 7, half = e & 1;
            *(float4*)(prev_obase + (size_t)sl2 * (NTREE * NCLS) + tg * NCLS + half * 4) = vreg[j];
        }
    }
}

extern "C" void kernel_launch(void* const* d_in, const int* in_sizes, int n_in,
                              void* d_out, int out_size) {
    // metadata order: x, lefts, rights, features, thresholds, values, nodes_offset
    const float* x          = (const float*)d_in[0];
    const int*   features   = (const int*)  d_in[3];
    const float* thresholds = (const float*)d_in[4];
    const float* values     = (const float*)d_in[5];

    static int nsm = 0;                        // deterministic per-device constant
    if (nsm == 0) {
        int dev = 0;
        cudaGetDevice(&dev);
        cudaDeviceGetAttribute(&nsm, cudaDevAttrMultiProcessorCount, dev);
        if (nsm <= 0) nsm = 148;
    }

    cudaFuncSetAttribute(traverse_k, cudaFuncAttributeMaxDynamicSharedMemorySize, SM_TOTAL);

    traverse_k<<<nsm, THREADS, SM_TOTAL>>>(x, features, thresholds, values,
                                           (float*)d_out, nsm);
}

// round 14
// speedup vs baseline: 1.0916x; 1.0916x over previous
#include <cuda_runtime.h>
#include <stdint.h>

#define BATCH   32768
#define NTREE   256
#define NNODE   2047
#define NFEAT   256
#define NCLS    8
#define DEPTH   10
#define SCHUNK  128
#define THREADS 512           // 128 samples x 4 tree-lanes (2 chains each)
#define GTREES  8
#define NCHUNK  (BATCH / SCHUNK)          // 256
#define NGROUPS (NTREE / GTREES)          // 32
#define NITEMS  (NCHUNK * NGROUPS)        // 8192, chunk-major
#define NSLOT   1024          // 8KB slab per tree (1023 internal nodes used)
#define GRPBYTES (GTREES * NSLOT * 8)     // 65536

// smem map: [0,128K) x-tile | [128K,192K) node buffer | [192K,+9K) idx x2 | mbar
#define SM_X      0
#define SM_NODES  131072
#define SM_IDX    196608
#define IDX_PITCH 9
#define IDX_BYTES (SCHUNK * IDX_PITCH * 4)   // 4608
#define SM_MBAR   (196608 + 2 * IDX_BYTES)
#define SM_TOTAL  (SM_MBAR + 16)

__device__ uint2 g_nodes2[NTREE * NSLOT];   // internal nodes: {thr bits, feat*512}
__device__ float g_xT[NFEAT * BATCH];       // x transposed [feature][sample]

// ---------------- merged prep: transpose x + pack nodes ----------------
__global__ void prep_k(const float* __restrict__ x,
                       const int* __restrict__ features,
                       const float* __restrict__ thresholds) {
    int b = blockIdx.x;
    const int TBLK = (NFEAT / 32) * (BATCH / 32);
    if (b < TBLK) {
        __shared__ float tile[32][33];
        int f0 = (b & 7) * 32, s0 = (b >> 3) * 32;
        int lx = threadIdx.x & 31, ly = threadIdx.x >> 5;   // 256 threads
        #pragma unroll
        for (int k = ly; k < 32; k += 8)
            tile[k][lx] = x[(size_t)(s0 + k) * NFEAT + f0 + lx];
        __syncthreads();
        #pragma unroll
        for (int k = ly; k < 32; k += 8)
            g_xT[(size_t)(f0 + k) * BATCH + s0 + lx] = tile[lx][k];
    } else {
        int i = (b - TBLK) * 256 + threadIdx.x;
        if (i < NTREE * 1023) {
            int t = i / 1023;
            int n = i - t * 1023;
            int src = t * NNODE + n;
            uint2 v;
            v.x = __float_as_uint(thresholds[src]);
            v.y = (unsigned)features[src] * (SCHUNK * 4);
            g_nodes2[t * NSLOT + n] = v;
        }
    }
    // PDL: allow the dependent traverse_k grid to begin launching
    asm volatile("griddepcontrol.launch_dependents;");
}

// ---------------- helpers ----------------
__device__ __forceinline__ void stage_x(char* sm, int s0, int tid) {
    float4* xs4 = (float4*)(sm + SM_X);
    #pragma unroll
    for (int j = 0; j < 16; j++) {
        int i4 = tid + THREADS * j;                 // 8192 float4
        int f = i4 >> 5, o = i4 & 31;
        xs4[i4] = *(const float4*)(g_xT + (size_t)f * BATCH + s0 + o * 4);
    }
}

__device__ __forceinline__ void bulk_fetch_nodes(unsigned dst, int g, unsigned mbar) {
    // one-shot 64KB DMA: expect_tx + bulk copy (caller: single thread)
    asm volatile("mbarrier.arrive.expect_tx.shared.b64 _, [%0], %1;"
                 :: "r"(mbar), "r"((unsigned)GRPBYTES) : "memory");
    const char* src = (const char*)g_nodes2 + (size_t)g * GRPBYTES;
    asm volatile("cp.async.bulk.shared::cta.global.mbarrier::complete_tx::bytes "
                 "[%0], [%1], %2, [%3];"
                 :: "r"(dst), "l"(src), "r"((unsigned)GRPBYTES), "r"(mbar) : "memory");
}

__device__ __forceinline__ void mbar_wait(unsigned mbar, unsigned parity) {
    unsigned done;
    asm volatile("{\n\t.reg .pred p;\n\t"
                 "mbarrier.try_wait.parity.acquire.cta.shared::cta.b64 p, [%1], %2;\n\t"
                 "selp.b32 %0, 1, 0, p;\n\t}"
                 : "=r"(done) : "r"(mbar), "r"(parity) : "memory");
    if (!done) {
        asm volatile("{\n\t.reg .pred P1;\n\t"
                     "W%=:\n\t"
                     "mbarrier.try_wait.parity.acquire.cta.shared::cta.b64 P1, [%0], %1, 0x989680;\n\t"
                     "@P1 bra.uni D%=;\n\t"
                     "bra.uni W%=;\n\t"
                     "D%=:\n\t}"
                     :: "r"(mbar), "r"(parity) : "memory");
    }
}

// ---------------- main traversal (persistent) ----------------
__global__ __launch_bounds__(THREADS, 1)
void traverse_k(const float* __restrict__ values, float* __restrict__ out, int nsm) {
    extern __shared__ char sm[];
    int tid = threadIdx.x;

    unsigned smbase;
    asm("{ .reg .u64 t; cvta.to.shared.u64 t, %1; cvt.u32.u64 %0, t; }"
        : "=r"(smbase) : "l"(sm));
    unsigned mbar = smbase + SM_MBAR;

    int istart = (int)((long long)blockIdx.x * NITEMS / nsm);
    int iend   = (int)((long long)(blockIdx.x + 1) * NITEMS / nsm);

    int sl = tid & (SCHUNK - 1);
    int tl = tid >> 7;                         // 0..3
    unsigned xaddr = smbase + SM_X + sl * 4;
    int tA = 2 * tl, tB = 2 * tl + 1;
    unsigned baseA = smbase + SM_NODES + tA * (NSLOT * 8);
    unsigned baseB = smbase + SM_NODES + tB * (NSLOT * 8);
    unsigned cA = 8u - baseA, cB = 8u - baseB;

    // prep-independent prologue (overlaps prep_k via PDL)
    if (tid == 0)
        asm volatile("mbarrier.init.shared.b64 [%0], 1;" :: "r"(mbar) : "memory");
    __syncthreads();

    // wait for prep_k's writes (g_xT, g_nodes2) to be visible
    asm volatile("griddepcontrol.wait;" ::: "memory");

    if (tid == 0) bulk_fetch_nodes(smbase + SM_NODES, istart & (NGROUPS - 1), mbar);
    int cur_chunk = istart >> 5;
    stage_x(sm, cur_chunk * SCHUNK, tid);
    __syncthreads();                            // x visible

    float4 vreg[4];
    float* prev_obase = out;

    for (int i = istart; i < iend; i++) {
        int k = i - istart;
        int chunk = i >> 5;
        int g = i & (NGROUPS - 1);
        int s0 = chunk * SCHUNK;
        int t0 = g * GTREES;

        if (chunk != cur_chunk) {               // all threads past prev barrier
            stage_x(sm, s0, tid);
            cur_chunk = chunk;
            __syncthreads();                    // x visible before traversal
        }

        // issue prev item's values gather (long-latency LDGs before the wait)
        if (i > istart) {
            const unsigned* rb = (const unsigned*)(sm + SM_IDX + ((i - 1) & 1) * IDX_BYTES);
            #pragma unroll
            for (int j = 0; j < 4; j++) {
                int e = tid + THREADS * j;
                int sl2 = e >> 4, tg = (e >> 1) & 7, half = e & 1;
                unsigned vrow = rb[sl2 * IDX_PITCH + tg];
                vreg[j] = __ldg((const float4*)values + (size_t)vrow * 2 + half);
            }
        }

        mbar_wait(mbar, (unsigned)(k & 1));     // nodes[i] staged (acquire)

        // ---- traversal: 2 interleaved chains, all loads from shared
        unsigned oA = baseA, oB = baseB;
        #pragma unroll
        for (int d = 0; d < DEPTH; d++) {
            unsigned ax, ay, bx, by;
            asm("ld.shared.v2.u32 {%0,%1}, [%2];" : "=r"(ax), "=r"(ay) : "r"(oA));
            asm("ld.shared.v2.u32 {%0,%1}, [%2];" : "=r"(bx), "=r"(by) : "r"(oB));
            float fa, fb;
            asm("ld.shared.f32 %0, [%1];" : "=f"(fa) : "r"(xaddr + ay));
            asm("ld.shared.f32 %0, [%1];" : "=f"(fb) : "r"(xaddr + by));
            oA = oA * 2u + cA + ((fa >= __uint_as_float(ax)) ? 8u : 0u);
            oB = oB * 2u + cB + ((fb >= __uint_as_float(bx)) ? 8u : 0u);
        }
        unsigned leafA = (oA - baseA) >> 3;     // 1023..2046
        unsigned leafB = (oB - baseB) >> 3;

        // ---- store prev item's gathered values (coalesced)
        if (i > istart) {
            #pragma unroll
            for (int j = 0; j < 4; j++) {
                int e = tid + THREADS * j;
                int sl2 = e >> 4, tg = (e >> 1) & 7, half = e & 1;
                *(float4*)(prev_obase + (size_t)sl2 * (NTREE * NCLS) + tg * NCLS + half * 4) = vreg[j];
            }
        }

        // ---- publish this item's values-row indices (pitch 9, conflict-free)
        {
            unsigned* wb = (unsigned*)(sm + SM_IDX + (i & 1) * IDX_BYTES);
            wb[sl * IDX_PITCH + tA] = (unsigned)(t0 + tA) * NNODE + leafA;
            wb[sl * IDX_PITCH + tB] = (unsigned)(t0 + tB) * NNODE + leafB;
        }
        __syncthreads();                        // idx visible; node reads done

        if (i + 1 < iend && tid == 0)
            bulk_fetch_nodes(smbase + SM_NODES, (i + 1) & (NGROUPS - 1), mbar);

        prev_obase = out + (size_t)s0 * (NTREE * NCLS) + t0 * NCLS;
    }

    // epilogue: gather + store for the last item
    {
        const unsigned* rb = (const unsigned*)(sm + SM_IDX + ((iend - 1) & 1) * IDX_BYTES);
        #pragma unroll
        for (int j = 0; j < 4; j++) {
            int e = tid + THREADS * j;
            int sl2 = e >> 4, tg = (e >> 1) & 7, half = e & 1;
            unsigned vrow = rb[sl2 * IDX_PITCH + tg];
            vreg[j] = __ldg((const float4*)values + (size_t)vrow * 2 + half);
        }
        #pragma unroll
        for (int j = 0; j < 4; j++) {
            int e = tid + THREADS * j;
            int sl2 = e >> 4, tg = (e >> 1) & 7, half = e & 1;
            *(float4*)(prev_obase + (size_t)sl2 * (NTREE * NCLS) + tg * NCLS + half * 4) = vreg[j];
        }
    }
}

extern "C" void kernel_launch(void* const* d_in, const int* in_sizes, int n_in,
                              void* d_out, int out_size) {
    // metadata order: x, lefts, rights, features, thresholds, values, nodes_offset
    const float* x          = (const float*)d_in[0];
    const int*   features   = (const int*)  d_in[3];
    const float* thresholds = (const float*)d_in[4];
    const float* values     = (const float*)d_in[5];

    static int nsm = 0;                        // deterministic per-device constant
    if (nsm == 0) {
        int dev = 0;
        cudaGetDevice(&dev);
        cudaDeviceGetAttribute(&nsm, cudaDevAttrMultiProcessorCount, dev);
        if (nsm <= 0) nsm = 148;
        cudaFuncSetAttribute(traverse_k, cudaFuncAttributeMaxDynamicSharedMemorySize, SM_TOTAL);
    }

    int prep_blocks = (NFEAT / 32) * (BATCH / 32) + (NTREE * 1023 + 255) / 256;
    prep_k<<<prep_blocks, 256>>>(x, features, thresholds);

    // traverse_k with Programmatic Dependent Launch: overlaps its launch/prologue
    // with prep_k; griddepcontrol.wait inside orders the g_xT/g_nodes2 reads.
    cudaLaunchConfig_t cfg = {};
    cfg.gridDim = dim3(nsm, 1, 1);
    cfg.blockDim = dim3(THREADS, 1, 1);
    cfg.dynamicSmemBytes = SM_TOTAL;
    cudaLaunchAttribute attrs[1];
    attrs[0].id = cudaLaunchAttributeProgrammaticStreamSerialization;
    attrs[0].val.programmaticStreamSerializationAllowed = 1;
    cfg.attrs = attrs;
    cfg.numAttrs = 1;
    cudaLaunchKernelEx(&cfg, traverse_k, values, (float*)d_out, nsm);
}